// round 15
// baseline (speedup 1.0000x reference)
#include <cuda_runtime.h>
#include <cuda_bf16.h>
#include <math.h>
#include <stdint.h>

#define BQ 4
#define NP 16384
#define SQ 2048
#define KNN 32
#define NQTOT (BQ*SQ)
#define MROWS (NQTOT*KNN)
#define RAD2 0.04f
#define BN_EPS 1e-5f

// smem row strides (bf16 units); chosen so ldmatrix 8-row groups are
// conflict-free (r*stride mod 128B distinct for r=0..7).
#define KS23 200
#define KS1  248

typedef unsigned long long ULL;

__device__ int   g_idx[MROWS];
__device__ float g_h1[(size_t)64*MROWS];    // [C][M]
__device__ float g_h2[(size_t)64*MROWS];    // [C][M]
__device__ float g_h3[(size_t)128*MROWS];   // [C][M]
__device__ float g_sum[3*128];
__device__ float g_sq[3*128];

// ---------------- helpers ----------------------------------------------------
__device__ __forceinline__ uint32_t smem_u32(const void* p) {
    uint32_t a;
    asm("{ .reg .u64 t; cvta.to.shared.u64 t, %1; cvt.u32.u64 %0, t; }"
        : "=r"(a) : "l"(p));
    return a;
}
__device__ __forceinline__ void sts128(uint32_t a, uint32_t x, uint32_t y,
                                       uint32_t z, uint32_t w) {
    asm volatile("st.shared.v4.b32 [%0], {%1,%2,%3,%4};"
                 :: "r"(a), "r"(x), "r"(y), "r"(z), "r"(w));
}
__device__ __forceinline__ void sts64(uint32_t a, uint32_t x, uint32_t y) {
    asm volatile("st.shared.v2.b32 [%0], {%1,%2};" :: "r"(a), "r"(x), "r"(y));
}
__device__ __forceinline__ void ldsm4(uint32_t a, uint32_t& r0, uint32_t& r1,
                                      uint32_t& r2, uint32_t& r3) {
    asm volatile("ldmatrix.sync.aligned.m8n8.x4.shared.b16 {%0,%1,%2,%3}, [%4];"
                 : "=r"(r0), "=r"(r1), "=r"(r2), "=r"(r3) : "r"(a));
}
__device__ __forceinline__ void mma16816(float* d, const uint32_t* a,
                                         const uint32_t* b) {
    asm volatile("mma.sync.aligned.m16n8k16.row.col.f32.bf16.bf16.f32 "
                 "{%0,%1,%2,%3}, {%4,%5,%6,%7}, {%8,%9}, {%0,%1,%2,%3};"
                 : "+f"(d[0]), "+f"(d[1]), "+f"(d[2]), "+f"(d[3])
                 : "r"(a[0]), "r"(a[1]), "r"(a[2]), "r"(a[3]),
                   "r"(b[0]), "r"(b[1]));
}
__device__ __forceinline__ void split2(float a, float b, uint32_t& h, uint32_t& l) {
    __nv_bfloat16 ah = __float2bfloat16(a);
    __nv_bfloat16 bh = __float2bfloat16(b);
    float al = a - __bfloat162float(ah);
    float bl = b - __bfloat162float(bh);
    h = (uint32_t)__bfloat16_as_ushort(ah)
      | ((uint32_t)__bfloat16_as_ushort(bh) << 16);
    l = (uint32_t)__bfloat16_as_ushort(__float2bfloat16(al))
      | ((uint32_t)__bfloat16_as_ushort(__float2bfloat16(bl)) << 16);
}
// Store channels [c0, c0+NCH) of one row, split into 3 K'-regions.
// MODE 0 (A): [h | l | h].  MODE 1 (B): [h | h | l].
template<int KP, int KS, int MODE, int NCH>
__device__ __forceinline__ void split_row_part(uint32_t base, int row, int c0,
                                               const float* v) {
    const uint32_t rb = base + (uint32_t)row * (KS*2);
    #pragma unroll
    for (int c = 0; c < NCH; c += 8) {
        uint32_t h0,l0,h1,l1,h2,l2,h3,l3;
        split2(v[c+0], v[c+1], h0, l0);
        split2(v[c+2], v[c+3], h1, l1);
        split2(v[c+4], v[c+5], h2, l2);
        split2(v[c+6], v[c+7], h3, l3);
        const int cc = c0 + c;
        sts128(rb + cc*2,          h0, h1, h2, h3);
        if (MODE == 0) {
            sts128(rb + (KP+cc)*2,   l0, l1, l2, l3);
            sts128(rb + (2*KP+cc)*2, h0, h1, h2, h3);
        } else {
            sts128(rb + (KP+cc)*2,   h0, h1, h2, h3);
            sts128(rb + (2*KP+cc)*2, l0, l1, l2, l3);
        }
    }
}

// ---------------- MMA core + channel-major epilogue with fused BN stats ------
// Tile: 128 rows x (NT*8) cols, 8 warps (warp = 16m x N n). K' = 16*NSTEP.
template<int NSTEP, int KS, int NT>
__device__ void mma_core_store(uint32_t aBase, uint32_t bBase,
                               const float* sbias, float* __restrict__ Yt,
                               int m0, float* s_sum, float* s_sq,
                               float* __restrict__ gsum,
                               float* __restrict__ gsq) {
    const int t = threadIdx.x, wid = t >> 5, lane = t & 31;
    uint32_t aAddr = aBase + ((uint32_t)(16*wid + (lane & 15)) * KS
                              + (uint32_t)(lane >> 4) * 8) * 2;
    uint32_t bAddr = bBase + ((uint32_t)((lane & 7) + ((lane >> 4) << 3)) * KS
                              + (uint32_t)(lane & 8)) * 2;
    float acc[NT][4];
    #pragma unroll
    for (int nt = 0; nt < NT; nt++)
        #pragma unroll
        for (int r = 0; r < 4; r++) acc[nt][r] = 0.f;

    #pragma unroll
    for (int ks = 0; ks < NSTEP; ks++) {
        uint32_t a[4];
        ldsm4(aAddr + ks*32, a[0], a[1], a[2], a[3]);
        #pragma unroll
        for (int h = 0; h < NT/8; h++) {      // B in 8-tile halves: caps regs
            uint32_t b[8][2];
            #pragma unroll
            for (int nb = 0; nb < 4; nb++) {
                uint32_t r0, r1, r2, r3;
                ldsm4(bAddr + (uint32_t)(h*4 + nb)*16*KS*2 + ks*32, r0, r1, r2, r3);
                b[2*nb][0] = r0;   b[2*nb][1] = r1;
                b[2*nb+1][0] = r2; b[2*nb+1][1] = r3;
            }
            #pragma unroll
            for (int n8 = 0; n8 < 8; n8++)
                mma16816(acc[h*8 + n8], a, b[n8]);
        }
    }
    const unsigned F = 0xffffffffu;
    const int g = lane >> 2, tg = lane & 3;
    const int rm = m0 + 16*wid + g;
    #pragma unroll
    for (int nt = 0; nt < NT; nt++) {
        const int c = 8*nt + 2*tg;
        const float b0 = sbias[c], b1 = sbias[c+1];
        float y0 = acc[nt][0] + b0;
        float y1 = acc[nt][1] + b1;
        float y2 = acc[nt][2] + b0;
        float y3 = acc[nt][3] + b1;
        Yt[(size_t)c*MROWS + rm]         = y0;
        Yt[(size_t)(c+1)*MROWS + rm]     = y1;
        Yt[(size_t)c*MROWS + rm + 8]     = y2;
        Yt[(size_t)(c+1)*MROWS + rm + 8] = y3;
        float s0 = y0 + y2, s1 = y1 + y3;
        float q0 = fmaf(y0, y0, __fmul_rn(y2, y2));
        float q1 = fmaf(y1, y1, __fmul_rn(y3, y3));
        #pragma unroll
        for (int mk = 4; mk <= 16; mk <<= 1) {
            s0 += __shfl_xor_sync(F, s0, mk);
            s1 += __shfl_xor_sync(F, s1, mk);
            q0 += __shfl_xor_sync(F, q0, mk);
            q1 += __shfl_xor_sync(F, q1, mk);
        }
        if (g == 0) {
            atomicAdd(&s_sum[c],   s0);
            atomicAdd(&s_sum[c+1], s1);
            atomicAdd(&s_sq[c],    q0);
            atomicAdd(&s_sq[c+1],  q1);
        }
    }
    __syncthreads();
    if (t < NT*8) {
        atomicAdd(&gsum[t], s_sum[t]);
        atomicAdd(&gsq[t],  s_sq[t]);
    }
}

// ---------------- stats reset -------------------------------------------------
__global__ void zero_stats_kernel() {
    int t = threadIdx.x + blockIdx.x * blockDim.x;
    if (t < 3*128) { g_sum[t] = 0.f; g_sq[t] = 0.f; }
}

// ---------------- ball query (FROZEN arithmetic) ------------------------------
__global__ void ballquery_kernel(const float* __restrict__ xyz,
                                 const float* __restrict__ newxyz, int blockOff) {
    int warp = (((blockIdx.x + blockOff) * blockDim.x) + threadIdx.x) >> 5;
    int lane = threadIdx.x & 31;
    if (warp >= NQTOT) return;
    int b = warp / SQ;
    const float* q = newxyz + (size_t)warp * 3;
    float qx = q[0], qy = q[1], qz = q[2];
    float qq = __fadd_rn(__fadd_rn(__fmul_rn(qx,qx), __fmul_rn(qy,qy)),
                         __fmul_rn(qz,qz));
    const float* xb = xyz + (size_t)b * NP * 3;
    int* outp = g_idx + (size_t)warp * KNN;
    int cnt = 0, first = -1;
    for (int base = 0; base < NP; base += 32) {
        int p = base + lane;
        float x = xb[p*3+0], y = xb[p*3+1], z = xb[p*3+2];
        float xx = __fadd_rn(__fadd_rn(__fmul_rn(x,x), __fmul_rn(y,y)),
                             __fmul_rn(z,z));
        float dt = fmaf(qz, z, fmaf(qy, y, __fmul_rn(qx, x)));
        float d2 = __fsub_rn(__fadd_rn(qq, xx), __fmul_rn(2.0f, dt));
        bool hit = !(d2 > RAD2);
        unsigned mask = __ballot_sync(0xffffffffu, hit);
        if (mask) {
            if (first < 0) first = base + __ffs(mask) - 1;
            int pos = cnt + __popc(mask & ((1u << lane) - 1u));
            if (hit && pos < KNN) outp[pos] = p;
            cnt += __popc(mask);
            if (cnt >= KNN) break;
        }
    }
    if (cnt < KNN) {
        if (first < 0) first = 0;
        for (int pos = cnt + lane; pos < KNN; pos += 32) outp[pos] = first;
    }
}

// ---------------- layer 1: gather + MMA (K=80 padded, K'=240) ----------------
__global__ void __launch_bounds__(256)
gemm1_tc(const float* __restrict__ xyz, const float* __restrict__ points,
         const float* __restrict__ newxyz, const float* __restrict__ W,
         const float* __restrict__ bias, float* __restrict__ Yt,
         float* __restrict__ gsum, float* __restrict__ gsq) {
    extern __shared__ __align__(16) char dyn[];
    __shared__ float sbias[64], s_sum[64], s_sq[64];
    const uint32_t aBase = smem_u32(dyn);
    const uint32_t bBase = aBase + 128 * KS1 * 2;
    const int t = threadIdx.x, m0 = blockIdx.x * 128;
    if (t < 64) { sbias[t] = bias[t]; s_sum[t] = 0.f; s_sq[t] = 0.f; }
    if (t < 64) {   // B row t: channels reordered [pts(0..63) | xyz(64..66) | 0]
        float w[80];
        #pragma unroll
        for (int i = 0; i < 64; i++) w[i] = W[t*67 + 3 + i];
        w[64] = W[t*67]; w[65] = W[t*67+1]; w[66] = W[t*67+2];
        #pragma unroll
        for (int i = 67; i < 80; i++) w[i] = 0.f;
        split_row_part<80, KS1, 1, 80>(bBase, t, 0, w);
    }
    {   // A gather: chunk k = t&15 (channels 4k..4k+3), 8 rows per thread
        const int k = t & 15, rb = t >> 4;      // rb 0..15
        const uint32_t colH = (uint32_t)(4*k) * 2;
        #pragma unroll 4
        for (int it = 0; it < 8; it++) {
            const int r = rb*8 + it;
            const int m = m0 + r;
            const int b = m >> 16;
            const int j = g_idx[m];
            float4 x = *((const float4*)(points + (size_t)(b*NP + j) * 64) + k);
            uint32_t h0, l0, h1, l1;
            split2(x.x, x.y, h0, l0);
            split2(x.z, x.w, h1, l1);
            const uint32_t rowB = aBase + (uint32_t)r * (KS1*2);
            sts64(rowB + colH,       h0, h1);
            sts64(rowB + 160 + colH, l0, l1);     // +80 cols
            sts64(rowB + 320 + colH, h0, h1);     // +160 cols
            if (k == 0) {   // xyz channels 64..66 + zero pad 67..79
                const int s = (m >> 5) & (SQ - 1);
                const float* pj = xyz    + (size_t)(b*NP + j) * 3;
                const float* qv = newxyz + (size_t)(b*SQ + s) * 3;
                float v[16];
                v[0] = pj[0]-qv[0]; v[1] = pj[1]-qv[1]; v[2] = pj[2]-qv[2];
                #pragma unroll
                for (int i = 3; i < 16; i++) v[i] = 0.f;
                uint32_t hh[8], ll[8];
                #pragma unroll
                for (int i = 0; i < 8; i++) split2(v[2*i], v[2*i+1], hh[i], ll[i]);
                sts128(rowB + 128, hh[0], hh[1], hh[2], hh[3]);
                sts128(rowB + 144, hh[4], hh[5], hh[6], hh[7]);
                sts128(rowB + 288, ll[0], ll[1], ll[2], ll[3]);
                sts128(rowB + 304, ll[4], ll[5], ll[6], ll[7]);
                sts128(rowB + 448, hh[0], hh[1], hh[2], hh[3]);
                sts128(rowB + 464, hh[4], hh[5], hh[6], hh[7]);
            }
        }
    }
    __syncthreads();
    mma_core_store<15, KS1, 8>(aBase, bBase, sbias, Yt, m0,
                               s_sum, s_sq, gsum, gsq);
}

// ---------------- layers 2/3: BN+ReLU fold + MMA (K=64, K'=192) --------------
// N = total output channels (64 or 128), single pass.
template<int N>
__global__ void __launch_bounds__(256)
gemm_bn_tc(const float* __restrict__ Xt, const float* __restrict__ W,
           const float* __restrict__ bias,
           const float* __restrict__ gammaP, const float* __restrict__ betaP,
           const float* __restrict__ gsumP, const float* __restrict__ gsqP,
           float* __restrict__ Yt,
           float* __restrict__ gsum, float* __restrict__ gsq) {
    extern __shared__ __align__(16) char dyn[];
    __shared__ float sbias[N], s_sum[N], s_sq[N], sscl[64], sshf[64];
    const uint32_t aBase = smem_u32(dyn);
    const uint32_t bBase = aBase + 128 * KS23 * 2;
    const int t = threadIdx.x, m0 = blockIdx.x * 128;
    if (t < N) { sbias[t] = bias[t]; s_sum[t] = 0.f; s_sq[t] = 0.f; }
    if (t < 64) {
        const float invM = 1.0f / (float)MROWS;
        float mean = gsumP[t] * invM;
        float var  = gsqP[t] * invM - mean*mean;
        float rs = rsqrtf(var + BN_EPS);
        float sc = gammaP[t] * rs;
        sscl[t] = sc; sshf[t] = betaP[t] - mean*sc;
    }
    if (t < N) {   // B row t (does not read sscl/sshf)
        float w[64];
        const float4* wr = (const float4*)(W + (size_t)t * 64);
        #pragma unroll
        for (int kk = 0; kk < 16; kk++) {
            float4 x = wr[kk];
            w[4*kk] = x.x; w[4*kk+1] = x.y; w[4*kk+2] = x.z; w[4*kk+3] = x.w;
        }
        split_row_part<64, KS23, 1, 64>(bBase, t, 0, w);
    }
    __syncthreads();   // sscl/sshf ready for all threads
    {   // A: 2 threads per row, 32 channels each; lane-coalesced LDG
        const int r = t >> 1, half = t & 1;
        const int m = m0 + r, c0 = 32*half;
        float v[32];
        #pragma unroll
        for (int c = 0; c < 32; c++) v[c] = Xt[(size_t)(c0 + c) * MROWS + m];
        #pragma unroll
        for (int c = 0; c < 32; c++)
            v[c] = fmaxf(fmaf(v[c], sscl[c0 + c], sshf[c0 + c]), 0.f);
        split_row_part<64, KS23, 0, 32>(aBase, r, c0, v);
    }
    __syncthreads();
    mma_core_store<12, KS23, N/8>(aBase, bBase, sbias, Yt, m0,
                                  s_sum, s_sq, gsum, gsq);
}

// ---------------- BN3 + ReLU + max over K (h3 channel-major) -----------------
__global__ void maxpool_kernel(const float* __restrict__ gamma,
                               const float* __restrict__ beta,
                               float* __restrict__ out) {
    const int t = threadIdx.x;
    const int qi = t >> 2, og = t & 3;
    const int q = blockIdx.x * 32 + qi;
    const int b = q / SQ, s = q - b*SQ;
    const float invM = 1.0f / (float)MROWS;
    #pragma unroll 4
    for (int i = 0; i < 32; i++) {
        int o = og*32 + i;
        float mean = g_sum[256 + o] * invM;
        float var  = g_sq[256 + o] * invM - mean*mean;
        float rs = rsqrtf(var + BN_EPS);
        float sc = gamma[o] * rs;
        float sh = beta[o] - mean*sc;
        const float4* h = (const float4*)(g_h3 + (size_t)o * MROWS + (size_t)q * KNN);
        float mx = -3.402823466e38f;
        #pragma unroll
        for (int k = 0; k < 8; k++) {
            float4 x = h[k];
            mx = fmaxf(mx, fmaf(x.x, sc, sh));
            mx = fmaxf(mx, fmaf(x.y, sc, sh));
            mx = fmaxf(mx, fmaf(x.z, sc, sh));
            mx = fmaxf(mx, fmaf(x.w, sc, sh));
        }
        out[(size_t)(b*128 + o) * SQ + s] = fmaxf(mx, 0.f);
    }
}

// ---------------- launch ------------------------------------------------
extern "C" void kernel_launch(void* const* d_in, const int* in_sizes, int n_in,
                              void* d_out, int out_size) {
    const float* xyz    = (const float*)d_in[0];
    const float* points = (const float*)d_in[1];
    const float* newxyz = (const float*)d_in[2];
    const float* W1 = (const float*)d_in[3],  *b1 = (const float*)d_in[4];
    const float* ga1 = (const float*)d_in[5], *be1 = (const float*)d_in[6];
    const float* W2 = (const float*)d_in[7],  *b2 = (const float*)d_in[8];
    const float* ga2 = (const float*)d_in[9], *be2 = (const float*)d_in[10];
    const float* W3 = (const float*)d_in[11], *b3 = (const float*)d_in[12];
    const float* ga3 = (const float*)d_in[13], *be3 = (const float*)d_in[14];

    float* out = (float*)d_out;
    float* outPts = out;
    if (out_size == BQ*SQ*3 + BQ*128*SQ) {
        cudaMemcpyAsync(out, newxyz, sizeof(float)*BQ*SQ*3, cudaMemcpyDeviceToDevice);
        outPts = out + BQ*SQ*3;
    }

    float *h1, *h2, *h3, *gsum, *gsq;
    cudaGetSymbolAddress((void**)&h1, g_h1);
    cudaGetSymbolAddress((void**)&h2, g_h2);
    cudaGetSymbolAddress((void**)&h3, g_h3);
    cudaGetSymbolAddress((void**)&gsum, g_sum);
    cudaGetSymbolAddress((void**)&gsq, g_sq);

    const int SM1 = 128*KS1*2 + 64*KS1*2;      // 95,232 B
    const int SM2 = 128*KS23*2 + 64*KS23*2;    // 76,800 B
    const int SM3 = 128*KS23*2 + 128*KS23*2;   // 102,400 B
    cudaFuncSetAttribute(gemm1_tc,        cudaFuncAttributeMaxDynamicSharedMemorySize, SM1);
    cudaFuncSetAttribute(gemm_bn_tc<64>,  cudaFuncAttributeMaxDynamicSharedMemorySize, SM2);
    cudaFuncSetAttribute(gemm_bn_tc<128>, cudaFuncAttributeMaxDynamicSharedMemorySize, SM3);

    // Launch order: ncu (-s 5 -c 1) profiles #6 = layer-3 GEMM.
    zero_stats_kernel<<<1, 512>>>();                                    // 1
    ballquery_kernel<<<512, 256>>>(xyz, newxyz, 0);                     // 2
    ballquery_kernel<<<512, 256>>>(xyz, newxyz, 512);                   // 3
    gemm1_tc<<<MROWS/128, 256, SM1>>>(xyz, points, newxyz, W1, b1, h1,
                                      gsum + 0, gsq + 0);               // 4
    gemm_bn_tc<64><<<MROWS/128, 256, SM2>>>(h1, W2, b2, ga1, be1,
                                            gsum + 0, gsq + 0, h2,
                                            gsum + 128, gsq + 128);     // 5
    gemm_bn_tc<128><<<MROWS/128, 256, SM3>>>(h2, W3, b3, ga2, be2,
                                             gsum + 128, gsq + 128, h3,
                                             gsum + 256, gsq + 256);    // 6
    maxpool_kernel<<<NQTOT/32, 128>>>(ga3, be3, outPts);                // 7
}

// round 16
// speedup vs baseline: 1.0675x; 1.0675x over previous
#include <cuda_runtime.h>
#include <cuda_bf16.h>
#include <math.h>
#include <stdint.h>

#define BQ 4
#define NP 16384
#define SQ 2048
#define KNN 32
#define NQTOT (BQ*SQ)
#define MROWS (NQTOT*KNN)
#define RAD2 0.04f
#define BN_EPS 1e-5f

// smem row strides (bf16 units); odd multiples of 8 -> conflict-free ldmatrix.
#define KS23 200
#define KS1  248

typedef unsigned long long ULL;

__device__ int   g_idx[MROWS];
__device__ float g_h1[(size_t)64*MROWS];    // [C][M]
__device__ float g_h2[(size_t)64*MROWS];    // [C][M]
__device__ float g_h3[(size_t)128*MROWS];   // [C][M]
__device__ float g_sum[3*128];
__device__ float g_sq[3*128];

// ---------------- helpers ----------------------------------------------------
__device__ __forceinline__ uint32_t smem_u32(const void* p) {
    uint32_t a;
    asm("{ .reg .u64 t; cvta.to.shared.u64 t, %1; cvt.u32.u64 %0, t; }"
        : "=r"(a) : "l"(p));
    return a;
}
__device__ __forceinline__ void sts128(uint32_t a, uint32_t x, uint32_t y,
                                       uint32_t z, uint32_t w) {
    asm volatile("st.shared.v4.b32 [%0], {%1,%2,%3,%4};"
                 :: "r"(a), "r"(x), "r"(y), "r"(z), "r"(w));
}
__device__ __forceinline__ void sts64(uint32_t a, uint32_t x, uint32_t y) {
    asm volatile("st.shared.v2.b32 [%0], {%1,%2};" :: "r"(a), "r"(x), "r"(y));
}
__device__ __forceinline__ void ldsm4(uint32_t a, uint32_t& r0, uint32_t& r1,
                                      uint32_t& r2, uint32_t& r3) {
    asm volatile("ldmatrix.sync.aligned.m8n8.x4.shared.b16 {%0,%1,%2,%3}, [%4];"
                 : "=r"(r0), "=r"(r1), "=r"(r2), "=r"(r3) : "r"(a));
}
__device__ __forceinline__ void mma16816(float* d, const uint32_t* a,
                                         const uint32_t* b) {
    asm volatile("mma.sync.aligned.m16n8k16.row.col.f32.bf16.bf16.f32 "
                 "{%0,%1,%2,%3}, {%4,%5,%6,%7}, {%8,%9}, {%0,%1,%2,%3};"
                 : "+f"(d[0]), "+f"(d[1]), "+f"(d[2]), "+f"(d[3])
                 : "r"(a[0]), "r"(a[1]), "r"(a[2]), "r"(a[3]),
                   "r"(b[0]), "r"(b[1]));
}
__device__ __forceinline__ void split2(float a, float b, uint32_t& h, uint32_t& l) {
    __nv_bfloat16 ah = __float2bfloat16(a);
    __nv_bfloat16 bh = __float2bfloat16(b);
    float al = a - __bfloat162float(ah);
    float bl = b - __bfloat162float(bh);
    h = (uint32_t)__bfloat16_as_ushort(ah)
      | ((uint32_t)__bfloat16_as_ushort(bh) << 16);
    l = (uint32_t)__bfloat16_as_ushort(__float2bfloat16(al))
      | ((uint32_t)__bfloat16_as_ushort(__float2bfloat16(bl)) << 16);
}
// Store channels [c0, c0+NCH) of one row, split into 3 K'-regions.
// MODE 0 (A): [h | l | h].  MODE 1 (B): [h | h | l].
template<int KP, int KS, int MODE, int NCH>
__device__ __forceinline__ void split_row_part(uint32_t base, int row, int c0,
                                               const float* v) {
    const uint32_t rb = base + (uint32_t)row * (KS*2);
    #pragma unroll
    for (int c = 0; c < NCH; c += 8) {
        uint32_t h0,l0,h1,l1,h2,l2,h3,l3;
        split2(v[c+0], v[c+1], h0, l0);
        split2(v[c+2], v[c+3], h1, l1);
        split2(v[c+4], v[c+5], h2, l2);
        split2(v[c+6], v[c+7], h3, l3);
        const int cc = c0 + c;
        sts128(rb + cc*2,          h0, h1, h2, h3);
        if (MODE == 0) {
            sts128(rb + (KP+cc)*2,   l0, l1, l2, l3);
            sts128(rb + (2*KP+cc)*2, h0, h1, h2, h3);
        } else {
            sts128(rb + (KP+cc)*2,   h0, h1, h2, h3);
            sts128(rb + (2*KP+cc)*2, l0, l1, l2, l3);
        }
    }
}

// ---------------- MMA core + channel-major epilogue --------------------------
// Tile: 128 rows x (NT*8) cols, 8 warps (warp = 16m x NT*8 n). K' = 16*NSTEP.
template<int NSTEP, int KS, int NT>
__device__ void mma_core_store(uint32_t aBase, uint32_t bBase,
                               const float* sbias, float* __restrict__ Yt,
                               int m0) {
    const int t = threadIdx.x, wid = t >> 5, lane = t & 31;
    uint32_t aAddr = aBase + ((uint32_t)(16*wid + (lane & 15)) * KS
                              + (uint32_t)(lane >> 4) * 8) * 2;
    uint32_t bAddr = bBase + ((uint32_t)((lane & 7) + ((lane >> 4) << 3)) * KS
                              + (uint32_t)(lane & 8)) * 2;
    float acc[NT][4];
    #pragma unroll
    for (int nt = 0; nt < NT; nt++)
        #pragma unroll
        for (int r = 0; r < 4; r++) acc[nt][r] = 0.f;

    #pragma unroll
    for (int ks = 0; ks < NSTEP; ks++) {
        uint32_t a[4];
        ldsm4(aAddr + ks*32, a[0], a[1], a[2], a[3]);
        #pragma unroll
        for (int h = 0; h < NT/8; h++) {      // B in 8-tile halves: caps regs
            uint32_t b[8][2];
            #pragma unroll
            for (int nb = 0; nb < 4; nb++) {
                uint32_t r0, r1, r2, r3;
                ldsm4(bAddr + (uint32_t)(h*4 + nb)*16*KS*2 + ks*32, r0, r1, r2, r3);
                b[2*nb][0] = r0;   b[2*nb][1] = r1;
                b[2*nb+1][0] = r2; b[2*nb+1][1] = r3;
            }
            #pragma unroll
            for (int n8 = 0; n8 < 8; n8++)
                mma16816(acc[h*8 + n8], a, b[n8]);
        }
    }
    const int g = lane >> 2, tg = lane & 3;
    const int rm = m0 + 16*wid + g;
    #pragma unroll
    for (int nt = 0; nt < NT; nt++) {
        const int c = 8*nt + 2*tg;
        const float b0 = sbias[c], b1 = sbias[c+1];
        Yt[(size_t)c*MROWS + rm]         = acc[nt][0] + b0;
        Yt[(size_t)(c+1)*MROWS + rm]     = acc[nt][1] + b1;
        Yt[(size_t)c*MROWS + rm + 8]     = acc[nt][2] + b0;
        Yt[(size_t)(c+1)*MROWS + rm + 8] = acc[nt][3] + b1;
    }
}

// ---------------- stats reset -------------------------------------------------
__global__ void zero_stats_kernel() {
    int t = threadIdx.x + blockIdx.x * blockDim.x;
    if (t < 3*128) { g_sum[t] = 0.f; g_sq[t] = 0.f; }
}

// ---------------- ball query (FROZEN arithmetic) ------------------------------
__global__ void ballquery_kernel(const float* __restrict__ xyz,
                                 const float* __restrict__ newxyz, int blockOff) {
    int warp = (((blockIdx.x + blockOff) * blockDim.x) + threadIdx.x) >> 5;
    int lane = threadIdx.x & 31;
    if (warp >= NQTOT) return;
    int b = warp / SQ;
    const float* q = newxyz + (size_t)warp * 3;
    float qx = q[0], qy = q[1], qz = q[2];
    float qq = __fadd_rn(__fadd_rn(__fmul_rn(qx,qx), __fmul_rn(qy,qy)),
                         __fmul_rn(qz,qz));
    const float* xb = xyz + (size_t)b * NP * 3;
    int* outp = g_idx + (size_t)warp * KNN;
    int cnt = 0, first = -1;
    for (int base = 0; base < NP; base += 32) {
        int p = base + lane;
        float x = xb[p*3+0], y = xb[p*3+1], z = xb[p*3+2];
        float xx = __fadd_rn(__fadd_rn(__fmul_rn(x,x), __fmul_rn(y,y)),
                             __fmul_rn(z,z));
        float dt = fmaf(qz, z, fmaf(qy, y, __fmul_rn(qx, x)));
        float d2 = __fsub_rn(__fadd_rn(qq, xx), __fmul_rn(2.0f, dt));
        bool hit = !(d2 > RAD2);
        unsigned mask = __ballot_sync(0xffffffffu, hit);
        if (mask) {
            if (first < 0) first = base + __ffs(mask) - 1;
            int pos = cnt + __popc(mask & ((1u << lane) - 1u));
            if (hit && pos < KNN) outp[pos] = p;
            cnt += __popc(mask);
            if (cnt >= KNN) break;
        }
    }
    if (cnt < KNN) {
        if (first < 0) first = 0;
        for (int pos = cnt + lane; pos < KNN; pos += 32) outp[pos] = first;
    }
}

// ---------------- layer 1: gather + MMA (K=80 padded, K'=240) ----------------
__global__ void __launch_bounds__(256)
gemm1_tc(const float* __restrict__ xyz, const float* __restrict__ points,
         const float* __restrict__ newxyz, const float* __restrict__ W,
         const float* __restrict__ bias, float* __restrict__ Yt) {
    extern __shared__ __align__(16) char dyn[];
    __shared__ float sbias[64];
    const uint32_t aBase = smem_u32(dyn);
    const uint32_t bBase = aBase + 128 * KS1 * 2;
    const int t = threadIdx.x, m0 = blockIdx.x * 128;
    if (t < 64) sbias[t] = bias[t];
    if (t < 64) {   // B row t: channels reordered [pts(0..63) | xyz(64..66) | 0]
        float w[80];
        #pragma unroll
        for (int i = 0; i < 64; i++) w[i] = W[t*67 + 3 + i];
        w[64] = W[t*67]; w[65] = W[t*67+1]; w[66] = W[t*67+2];
        #pragma unroll
        for (int i = 67; i < 80; i++) w[i] = 0.f;
        split_row_part<80, KS1, 1, 80>(bBase, t, 0, w);
    }
    {   // A gather: chunk k = t&15 (channels 4k..4k+3), 8 rows per thread
        const int k = t & 15, rb = t >> 4;      // rb 0..15
        const uint32_t colH = (uint32_t)(4*k) * 2;
        #pragma unroll 4
        for (int it = 0; it < 8; it++) {
            const int r = rb*8 + it;
            const int m = m0 + r;
            const int b = m >> 16;
            const int j = g_idx[m];
            float4 x = *((const float4*)(points + (size_t)(b*NP + j) * 64) + k);
            uint32_t h0, l0, h1, l1;
            split2(x.x, x.y, h0, l0);
            split2(x.z, x.w, h1, l1);
            const uint32_t rowB = aBase + (uint32_t)r * (KS1*2);
            sts64(rowB + colH,       h0, h1);
            sts64(rowB + 160 + colH, l0, l1);     // +80 cols
            sts64(rowB + 320 + colH, h0, h1);     // +160 cols
            if (k == 0) {   // xyz channels 64..66 + zero pad 67..79
                const int s = (m >> 5) & (SQ - 1);
                const float* pj = xyz    + (size_t)(b*NP + j) * 3;
                const float* qv = newxyz + (size_t)(b*SQ + s) * 3;
                float v[16];
                v[0] = pj[0]-qv[0]; v[1] = pj[1]-qv[1]; v[2] = pj[2]-qv[2];
                #pragma unroll
                for (int i = 3; i < 16; i++) v[i] = 0.f;
                uint32_t hh[8], ll[8];
                #pragma unroll
                for (int i = 0; i < 8; i++) split2(v[2*i], v[2*i+1], hh[i], ll[i]);
                sts128(rowB + 128, hh[0], hh[1], hh[2], hh[3]);
                sts128(rowB + 144, hh[4], hh[5], hh[6], hh[7]);
                sts128(rowB + 288, ll[0], ll[1], ll[2], ll[3]);
                sts128(rowB + 304, ll[4], ll[5], ll[6], ll[7]);
                sts128(rowB + 448, hh[0], hh[1], hh[2], hh[3]);
                sts128(rowB + 464, hh[4], hh[5], hh[6], hh[7]);
            }
        }
    }
    __syncthreads();
    mma_core_store<15, KS1, 8>(aBase, bBase, sbias, Yt, m0);
}

// ---------------- layers 2/3: BN+ReLU fold + MMA (K=64, K'=192) --------------
// N = total output channels (64 or 128), single pass.
template<int N>
__global__ void __launch_bounds__(256)
gemm_bn_tc(const float* __restrict__ Xt, const float* __restrict__ W,
           const float* __restrict__ bias,
           const float* __restrict__ gammaP, const float* __restrict__ betaP,
           const float* __restrict__ gsumP, const float* __restrict__ gsqP,
           float* __restrict__ Yt) {
    extern __shared__ __align__(16) char dyn[];
    __shared__ float sbias[N], sscl[64], sshf[64];
    const uint32_t aBase = smem_u32(dyn);
    const uint32_t bBase = aBase + 128 * KS23 * 2;
    const int t = threadIdx.x, m0 = blockIdx.x * 128;
    if (t < N) sbias[t] = bias[t];
    if (t < 64) {
        const float invM = 1.0f / (float)MROWS;
        float mean = gsumP[t] * invM;
        float var  = gsqP[t] * invM - mean*mean;
        float rs = rsqrtf(var + BN_EPS);
        float sc = gammaP[t] * rs;
        sscl[t] = sc; sshf[t] = betaP[t] - mean*sc;
    }
    if (t < N) {   // B row t (does not read sscl/sshf)
        float w[64];
        const float4* wr = (const float4*)(W + (size_t)t * 64);
        #pragma unroll
        for (int kk = 0; kk < 16; kk++) {
            float4 x = wr[kk];
            w[4*kk] = x.x; w[4*kk+1] = x.y; w[4*kk+2] = x.z; w[4*kk+3] = x.w;
        }
        split_row_part<64, KS23, 1, 64>(bBase, t, 0, w);
    }
    __syncthreads();   // sscl/sshf ready for all threads
    {   // A: 2 threads per row, 32 channels each; lane-coalesced LDG
        const int r = t >> 1, half = t & 1;
        const int m = m0 + r, c0 = 32*half;
        float v[32];
        #pragma unroll
        for (int c = 0; c < 32; c++) v[c] = Xt[(size_t)(c0 + c) * MROWS + m];
        #pragma unroll
        for (int c = 0; c < 32; c++)
            v[c] = fmaxf(fmaf(v[c], sscl[c0 + c], sshf[c0 + c]), 0.f);
        split_row_part<64, KS23, 0, 32>(aBase, r, c0, v);
    }
    __syncthreads();
    mma_core_store<12, KS23, N/8>(aBase, bBase, sbias, Yt, m0);
}

// ---------------- per-channel stats over Yt [C][MROWS] ------------------------
__global__ void stats_kernel(const float* __restrict__ Yt,
                             float* __restrict__ gsum, float* __restrict__ gsq) {
    const int c = blockIdx.x, t = threadIdx.x;
    const float4* p = (const float4*)(Yt + (size_t)c * MROWS
                                      + (size_t)blockIdx.y * 16384) + t;
    float s = 0.f, q = 0.f;
    #pragma unroll
    for (int i = 0; i < 16; i++) {
        float4 x = p[i * 256];
        s += (x.x + x.y) + (x.z + x.w);
        q = fmaf(x.x,x.x,q); q = fmaf(x.y,x.y,q);
        q = fmaf(x.z,x.z,q); q = fmaf(x.w,x.w,q);
    }
    const unsigned F = 0xffffffffu;
    #pragma unroll
    for (int o = 16; o > 0; o >>= 1) {
        s += __shfl_xor_sync(F, s, o);
        q += __shfl_xor_sync(F, q, o);
    }
    __shared__ float ws[8], wq[8];
    if ((t & 31) == 0) { ws[t>>5] = s; wq[t>>5] = q; }
    __syncthreads();
    if (t == 0) {
        float S = 0.f, Q = 0.f;
        #pragma unroll
        for (int i = 0; i < 8; i++) { S += ws[i]; Q += wq[i]; }
        atomicAdd(&gsum[c], S);
        atomicAdd(&gsq[c], Q);
    }
}

// ---------------- BN3 + ReLU + max over K (h3 channel-major) -----------------
__global__ void maxpool_kernel(const float* __restrict__ gamma,
                               const float* __restrict__ beta,
                               float* __restrict__ out) {
    const int t = threadIdx.x;
    const int qi = t >> 2, og = t & 3;
    const int q = blockIdx.x * 32 + qi;
    const int b = q / SQ, s = q - b*SQ;
    const float invM = 1.0f / (float)MROWS;
    #pragma unroll 4
    for (int i = 0; i < 32; i++) {
        int o = og*32 + i;
        float mean = g_sum[256 + o] * invM;
        float var  = g_sq[256 + o] * invM - mean*mean;
        float rs = rsqrtf(var + BN_EPS);
        float sc = gamma[o] * rs;
        float sh = beta[o] - mean*sc;
        const float4* h = (const float4*)(g_h3 + (size_t)o * MROWS + (size_t)q * KNN);
        float mx = -3.402823466e38f;
        #pragma unroll
        for (int k = 0; k < 8; k++) {
            float4 x = h[k];
            mx = fmaxf(mx, fmaf(x.x, sc, sh));
            mx = fmaxf(mx, fmaf(x.y, sc, sh));
            mx = fmaxf(mx, fmaf(x.z, sc, sh));
            mx = fmaxf(mx, fmaf(x.w, sc, sh));
        }
        out[(size_t)(b*128 + o) * SQ + s] = fmaxf(mx, 0.f);
    }
}

// ---------------- launch ------------------------------------------------
extern "C" void kernel_launch(void* const* d_in, const int* in_sizes, int n_in,
                              void* d_out, int out_size) {
    const float* xyz    = (const float*)d_in[0];
    const float* points = (const float*)d_in[1];
    const float* newxyz = (const float*)d_in[2];
    const float* W1 = (const float*)d_in[3],  *b1 = (const float*)d_in[4];
    const float* ga1 = (const float*)d_in[5], *be1 = (const float*)d_in[6];
    const float* W2 = (const float*)d_in[7],  *b2 = (const float*)d_in[8];
    const float* ga2 = (const float*)d_in[9], *be2 = (const float*)d_in[10];
    const float* W3 = (const float*)d_in[11], *b3 = (const float*)d_in[12];
    const float* ga3 = (const float*)d_in[13], *be3 = (const float*)d_in[14];

    float* out = (float*)d_out;
    float* outPts = out;
    if (out_size == BQ*SQ*3 + BQ*128*SQ) {
        cudaMemcpyAsync(out, newxyz, sizeof(float)*BQ*SQ*3, cudaMemcpyDeviceToDevice);
        outPts = out + BQ*SQ*3;
    }

    float *h1, *h2, *h3, *gsum, *gsq;
    cudaGetSymbolAddress((void**)&h1, g_h1);
    cudaGetSymbolAddress((void**)&h2, g_h2);
    cudaGetSymbolAddress((void**)&h3, g_h3);
    cudaGetSymbolAddress((void**)&gsum, g_sum);
    cudaGetSymbolAddress((void**)&gsq, g_sq);

    const int SM1 = 128*KS1*2 + 64*KS1*2;      // 95,232 B
    const int SM2 = 128*KS23*2 + 64*KS23*2;    // 76,800 B
    const int SM3 = 128*KS23*2 + 128*KS23*2;   // 102,400 B
    cudaFuncSetAttribute(gemm1_tc,        cudaFuncAttributeMaxDynamicSharedMemorySize, SM1);
    cudaFuncSetAttribute(gemm_bn_tc<64>,  cudaFuncAttributeMaxDynamicSharedMemorySize, SM2);
    cudaFuncSetAttribute(gemm_bn_tc<128>, cudaFuncAttributeMaxDynamicSharedMemorySize, SM3);

    // Launch order: ncu (-s 5 -c 1) profiles #6 = layer-2 GEMM.
    zero_stats_kernel<<<1, 512>>>();                                    // 1
    ballquery_kernel<<<512, 256>>>(xyz, newxyz, 0);                     // 2
    ballquery_kernel<<<512, 256>>>(xyz, newxyz, 512);                   // 3
    gemm1_tc<<<MROWS/128, 256, SM1>>>(xyz, points, newxyz, W1, b1, h1); // 4
    stats_kernel<<<dim3(64,16), 256>>>(h1, gsum + 0, gsq + 0);          // 5
    gemm_bn_tc<64><<<MROWS/128, 256, SM2>>>(h1, W2, b2, ga1, be1,
                                            gsum + 0, gsq + 0, h2);     // 6
    stats_kernel<<<dim3(64,16), 256>>>(h2, gsum + 128, gsq + 128);      // 7
    gemm_bn_tc<128><<<MROWS/128, 256, SM3>>>(h2, W3, b3, ga2, be2,
                                             gsum + 128, gsq + 128, h3);// 8
    stats_kernel<<<dim3(128,16), 256>>>(h3, gsum + 256, gsq + 256);     // 9
    maxpool_kernel<<<NQTOT/32, 128>>>(ga3, be3, outPts);                // 10
}

// round 17
// speedup vs baseline: 1.0878x; 1.0191x over previous
#include <cuda_runtime.h>
#include <cuda_bf16.h>
#include <math.h>
#include <stdint.h>

#define BQ 4
#define NP 16384
#define SQ 2048
#define KNN 32
#define NQTOT (BQ*SQ)
#define MROWS (NQTOT*KNN)
#define RAD2 0.04f
#define BN_EPS 1e-5f

// smem row strides (bf16 units); odd multiples of 8 -> conflict-free ldmatrix.
#define KS23 200
#define KS1  248

typedef unsigned long long ULL;

__device__ int   g_idx[MROWS];
__device__ float g_h1[(size_t)64*MROWS];    // [C][M]
__device__ float g_h2[(size_t)64*MROWS];    // [C][M]
__device__ float g_h3[(size_t)128*MROWS];   // [C][M]
__device__ float g_sum[3*128];
__device__ float g_sq[3*128];

// ---------------- helpers ----------------------------------------------------
__device__ __forceinline__ uint32_t smem_u32(const void* p) {
    uint32_t a;
    asm("{ .reg .u64 t; cvta.to.shared.u64 t, %1; cvt.u32.u64 %0, t; }"
        : "=r"(a) : "l"(p));
    return a;
}
__device__ __forceinline__ void sts128(uint32_t a, uint32_t x, uint32_t y,
                                       uint32_t z, uint32_t w) {
    asm volatile("st.shared.v4.b32 [%0], {%1,%2,%3,%4};"
                 :: "r"(a), "r"(x), "r"(y), "r"(z), "r"(w));
}
__device__ __forceinline__ void sts64(uint32_t a, uint32_t x, uint32_t y) {
    asm volatile("st.shared.v2.b32 [%0], {%1,%2};" :: "r"(a), "r"(x), "r"(y));
}
__device__ __forceinline__ void ldsm4(uint32_t a, uint32_t& r0, uint32_t& r1,
                                      uint32_t& r2, uint32_t& r3) {
    asm volatile("ldmatrix.sync.aligned.m8n8.x4.shared.b16 {%0,%1,%2,%3}, [%4];"
                 : "=r"(r0), "=r"(r1), "=r"(r2), "=r"(r3) : "r"(a));
}
__device__ __forceinline__ void mma16816(float* d, const uint32_t* a,
                                         const uint32_t* b) {
    asm volatile("mma.sync.aligned.m16n8k16.row.col.f32.bf16.bf16.f32 "
                 "{%0,%1,%2,%3}, {%4,%5,%6,%7}, {%8,%9}, {%0,%1,%2,%3};"
                 : "+f"(d[0]), "+f"(d[1]), "+f"(d[2]), "+f"(d[3])
                 : "r"(a[0]), "r"(a[1]), "r"(a[2]), "r"(a[3]),
                   "r"(b[0]), "r"(b[1]));
}
__device__ __forceinline__ void split2(float a, float b, uint32_t& h, uint32_t& l) {
    __nv_bfloat16 ah = __float2bfloat16(a);
    __nv_bfloat16 bh = __float2bfloat16(b);
    float al = a - __bfloat162float(ah);
    float bl = b - __bfloat162float(bh);
    h = (uint32_t)__bfloat16_as_ushort(ah)
      | ((uint32_t)__bfloat16_as_ushort(bh) << 16);
    l = (uint32_t)__bfloat16_as_ushort(__float2bfloat16(al))
      | ((uint32_t)__bfloat16_as_ushort(__float2bfloat16(bl)) << 16);
}
// Store channels [c0, c0+NCH) of one row, split into 3 K'-regions.
// MODE 0 (A): [h | l | h].  MODE 1 (B): [h | h | l].
template<int KP, int KS, int MODE, int NCH>
__device__ __forceinline__ void split_row_part(uint32_t base, int row, int c0,
                                               const float* v) {
    const uint32_t rb = base + (uint32_t)row * (KS*2);
    #pragma unroll
    for (int c = 0; c < NCH; c += 8) {
        uint32_t h0,l0,h1,l1,h2,l2,h3,l3;
        split2(v[c+0], v[c+1], h0, l0);
        split2(v[c+2], v[c+3], h1, l1);
        split2(v[c+4], v[c+5], h2, l2);
        split2(v[c+6], v[c+7], h3, l3);
        const int cc = c0 + c;
        sts128(rb + cc*2,          h0, h1, h2, h3);
        if (MODE == 0) {
            sts128(rb + (KP+cc)*2,   l0, l1, l2, l3);
            sts128(rb + (2*KP+cc)*2, h0, h1, h2, h3);
        } else {
            sts128(rb + (KP+cc)*2,   h0, h1, h2, h3);
            sts128(rb + (2*KP+cc)*2, l0, l1, l2, l3);
        }
    }
}

// ---------------- MMA core + channel-major epilogue --------------------------
// Tile: 128 rows x (NW*16) cols, 8 warps = 4 m-quarters x 2 n-halves.
// Warp = 32m x NW*8 n.  K' = 16*NSTEP.
template<int NSTEP, int KS, int NW>
__device__ void mma_core_store(uint32_t aBase, uint32_t bBase,
                               const float* sbias, float* __restrict__ Yt,
                               int m0) {
    const int t = threadIdx.x, wid = t >> 5, lane = t & 31;
    const int mq = wid >> 1, nh = wid & 1;
    uint32_t aAddr = aBase + ((uint32_t)(32*mq + (lane & 15)) * KS
                              + (uint32_t)(lane >> 4) * 8) * 2;
    uint32_t bAddr = bBase + ((uint32_t)((lane & 7) + ((lane >> 4) << 3)
                                         + nh*NW*8) * KS
                              + (uint32_t)(lane & 8)) * 2;
    float acc[2][NW][4];
    #pragma unroll
    for (int mt = 0; mt < 2; mt++)
        #pragma unroll
        for (int nt = 0; nt < NW; nt++)
            #pragma unroll
            for (int r = 0; r < 4; r++) acc[mt][nt][r] = 0.f;

    #pragma unroll
    for (int ks = 0; ks < NSTEP; ks++) {
        uint32_t a[2][4];
        ldsm4(aAddr + ks*32,           a[0][0], a[0][1], a[0][2], a[0][3]);
        ldsm4(aAddr + 16*KS*2 + ks*32, a[1][0], a[1][1], a[1][2], a[1][3]);
        #pragma unroll
        for (int h = 0; h < NW/4; h++) {      // B in 4-tile groups: caps regs
            uint32_t b[4][2];
            #pragma unroll
            for (int nb = 0; nb < 2; nb++) {
                uint32_t r0, r1, r2, r3;
                ldsm4(bAddr + (uint32_t)(h*2 + nb)*16*KS*2 + ks*32,
                      r0, r1, r2, r3);
                b[2*nb][0] = r0;   b[2*nb][1] = r1;
                b[2*nb+1][0] = r2; b[2*nb+1][1] = r3;
            }
            #pragma unroll
            for (int mt = 0; mt < 2; mt++)
                #pragma unroll
                for (int n4 = 0; n4 < 4; n4++)
                    mma16816(acc[mt][h*4 + n4], a[mt], b[n4]);
        }
    }
    const int g = lane >> 2, tg = lane & 3;
    #pragma unroll
    for (int mt = 0; mt < 2; mt++) {
        const int rm = m0 + 32*mq + 16*mt + g;
        #pragma unroll
        for (int nt = 0; nt < NW; nt++) {
            const int c = nh*NW*8 + 8*nt + 2*tg;
            const float b0 = sbias[c], b1 = sbias[c+1];
            Yt[(size_t)c*MROWS + rm]         = acc[mt][nt][0] + b0;
            Yt[(size_t)(c+1)*MROWS + rm]     = acc[mt][nt][1] + b1;
            Yt[(size_t)c*MROWS + rm + 8]     = acc[mt][nt][2] + b0;
            Yt[(size_t)(c+1)*MROWS + rm + 8] = acc[mt][nt][3] + b1;
        }
    }
}

// ---------------- stats reset -------------------------------------------------
__global__ void zero_stats_kernel() {
    int t = threadIdx.x + blockIdx.x * blockDim.x;
    if (t < 3*128) { g_sum[t] = 0.f; g_sq[t] = 0.f; }
}

// ---------------- ball query (FROZEN arithmetic) ------------------------------
__global__ void ballquery_kernel(const float* __restrict__ xyz,
                                 const float* __restrict__ newxyz, int blockOff) {
    int warp = (((blockIdx.x + blockOff) * blockDim.x) + threadIdx.x) >> 5;
    int lane = threadIdx.x & 31;
    if (warp >= NQTOT) return;
    int b = warp / SQ;
    const float* q = newxyz + (size_t)warp * 3;
    float qx = q[0], qy = q[1], qz = q[2];
    float qq = __fadd_rn(__fadd_rn(__fmul_rn(qx,qx), __fmul_rn(qy,qy)),
                         __fmul_rn(qz,qz));
    const float* xb = xyz + (size_t)b * NP * 3;
    int* outp = g_idx + (size_t)warp * KNN;
    int cnt = 0, first = -1;
    for (int base = 0; base < NP; base += 32) {
        int p = base + lane;
        float x = xb[p*3+0], y = xb[p*3+1], z = xb[p*3+2];
        float xx = __fadd_rn(__fadd_rn(__fmul_rn(x,x), __fmul_rn(y,y)),
                             __fmul_rn(z,z));
        float dt = fmaf(qz, z, fmaf(qy, y, __fmul_rn(qx, x)));
        float d2 = __fsub_rn(__fadd_rn(qq, xx), __fmul_rn(2.0f, dt));
        bool hit = !(d2 > RAD2);
        unsigned mask = __ballot_sync(0xffffffffu, hit);
        if (mask) {
            if (first < 0) first = base + __ffs(mask) - 1;
            int pos = cnt + __popc(mask & ((1u << lane) - 1u));
            if (hit && pos < KNN) outp[pos] = p;
            cnt += __popc(mask);
            if (cnt >= KNN) break;
        }
    }
    if (cnt < KNN) {
        if (first < 0) first = 0;
        for (int pos = cnt + lane; pos < KNN; pos += 32) outp[pos] = first;
    }
}

// ---------------- layer 1: gather + MMA (K=80 padded, K'=240) ----------------
__global__ void __launch_bounds__(256)
gemm1_tc(const float* __restrict__ xyz, const float* __restrict__ points,
         const float* __restrict__ newxyz, const float* __restrict__ W,
         const float* __restrict__ bias, float* __restrict__ Yt) {
    extern __shared__ __align__(16) char dyn[];
    __shared__ float sbias[64];
    const uint32_t aBase = smem_u32(dyn);
    const uint32_t bBase = aBase + 128 * KS1 * 2;
    const int t = threadIdx.x, m0 = blockIdx.x * 128;
    if (t < 64) sbias[t] = bias[t];
    if (t < 64) {   // B row t: channels reordered [pts(0..63) | xyz(64..66) | 0]
        float w[80];
        #pragma unroll
        for (int i = 0; i < 64; i++) w[i] = W[t*67 + 3 + i];
        w[64] = W[t*67]; w[65] = W[t*67+1]; w[66] = W[t*67+2];
        #pragma unroll
        for (int i = 67; i < 80; i++) w[i] = 0.f;
        split_row_part<80, KS1, 1, 80>(bBase, t, 0, w);
    }
    {   // A gather: chunk k = t&15 (channels 4k..4k+3), 8 rows per thread
        const int k = t & 15, rb = t >> 4;      // rb 0..15
        const uint32_t colH = (uint32_t)(4*k) * 2;
        #pragma unroll 4
        for (int it = 0; it < 8; it++) {
            const int r = rb*8 + it;
            const int m = m0 + r;
            const int b = m >> 16;
            const int j = g_idx[m];
            float4 x = *((const float4*)(points + (size_t)(b*NP + j) * 64) + k);
            uint32_t h0, l0, h1, l1;
            split2(x.x, x.y, h0, l0);
            split2(x.z, x.w, h1, l1);
            const uint32_t rowB = aBase + (uint32_t)r * (KS1*2);
            sts64(rowB + colH,       h0, h1);
            sts64(rowB + 160 + colH, l0, l1);     // +80 cols
            sts64(rowB + 320 + colH, h0, h1);     // +160 cols
            if (k == 0) {   // xyz channels 64..66 + zero pad 67..79
                const int s = (m >> 5) & (SQ - 1);
                const float* pj = xyz    + (size_t)(b*NP + j) * 3;
                const float* qv = newxyz + (size_t)(b*SQ + s) * 3;
                float v[16];
                v[0] = pj[0]-qv[0]; v[1] = pj[1]-qv[1]; v[2] = pj[2]-qv[2];
                #pragma unroll
                for (int i = 3; i < 16; i++) v[i] = 0.f;
                uint32_t hh[8], ll[8];
                #pragma unroll
                for (int i = 0; i < 8; i++) split2(v[2*i], v[2*i+1], hh[i], ll[i]);
                sts128(rowB + 128, hh[0], hh[1], hh[2], hh[3]);
                sts128(rowB + 144, hh[4], hh[5], hh[6], hh[7]);
                sts128(rowB + 288, ll[0], ll[1], ll[2], ll[3]);
                sts128(rowB + 304, ll[4], ll[5], ll[6], ll[7]);
                sts128(rowB + 448, hh[0], hh[1], hh[2], hh[3]);
                sts128(rowB + 464, hh[4], hh[5], hh[6], hh[7]);
            }
        }
    }
    __syncthreads();
    mma_core_store<15, KS1, 4>(aBase, bBase, sbias, Yt, m0);
}

// ---------------- layers 2/3: BN+ReLU fold + MMA (K=64, K'=192) --------------
// N = total output channels (64 or 128), single pass.
template<int N>
__global__ void __launch_bounds__(256)
gemm_bn_tc(const float* __restrict__ Xt, const float* __restrict__ W,
           const float* __restrict__ bias,
           const float* __restrict__ gammaP, const float* __restrict__ betaP,
           const float* __restrict__ gsumP, const float* __restrict__ gsqP,
           float* __restrict__ Yt) {
    extern __shared__ __align__(16) char dyn[];
    __shared__ float sbias[N], sscl[64], sshf[64];
    const uint32_t aBase = smem_u32(dyn);
    const uint32_t bBase = aBase + 128 * KS23 * 2;
    const int t = threadIdx.x, m0 = blockIdx.x * 128;
    if (t < N) sbias[t] = bias[t];
    if (t < 64) {
        const float invM = 1.0f / (float)MROWS;
        float mean = gsumP[t] * invM;
        float var  = gsqP[t] * invM - mean*mean;
        float rs = rsqrtf(var + BN_EPS);
        float sc = gammaP[t] * rs;
        sscl[t] = sc; sshf[t] = betaP[t] - mean*sc;
    }
    if (t < N) {   // B row t (does not read sscl/sshf)
        float w[64];
        const float4* wr = (const float4*)(W + (size_t)t * 64);
        #pragma unroll
        for (int kk = 0; kk < 16; kk++) {
            float4 x = wr[kk];
            w[4*kk] = x.x; w[4*kk+1] = x.y; w[4*kk+2] = x.z; w[4*kk+3] = x.w;
        }
        split_row_part<64, KS23, 1, 64>(bBase, t, 0, w);
    }
    __syncthreads();   // sscl/sshf ready for all threads
    {   // A: 2 threads per row, 32 channels each; lane-coalesced LDG
        const int r = t >> 1, half = t & 1;
        const int m = m0 + r, c0 = 32*half;
        float v[32];
        #pragma unroll
        for (int c = 0; c < 32; c++) v[c] = Xt[(size_t)(c0 + c) * MROWS + m];
        #pragma unroll
        for (int c = 0; c < 32; c++)
            v[c] = fmaxf(fmaf(v[c], sscl[c0 + c], sshf[c0 + c]), 0.f);
        split_row_part<64, KS23, 0, 32>(aBase, r, c0, v);
    }
    __syncthreads();
    mma_core_store<12, KS23, N/16>(aBase, bBase, sbias, Yt, m0);
}

// ---------------- per-channel stats over Yt [C][MROWS] ------------------------
__global__ void stats_kernel(const float* __restrict__ Yt,
                             float* __restrict__ gsum, float* __restrict__ gsq) {
    const int c = blockIdx.x, t = threadIdx.x;
    const float4* p = (const float4*)(Yt + (size_t)c * MROWS
                                      + (size_t)blockIdx.y * 16384) + t;
    float s = 0.f, q = 0.f;
    #pragma unroll
    for (int i = 0; i < 16; i++) {
        float4 x = p[i * 256];
        s += (x.x + x.y) + (x.z + x.w);
        q = fmaf(x.x,x.x,q); q = fmaf(x.y,x.y,q);
        q = fmaf(x.z,x.z,q); q = fmaf(x.w,x.w,q);
    }
    const unsigned F = 0xffffffffu;
    #pragma unroll
    for (int o = 16; o > 0; o >>= 1) {
        s += __shfl_xor_sync(F, s, o);
        q += __shfl_xor_sync(F, q, o);
    }
    __shared__ float ws[8], wq[8];
    if ((t & 31) == 0) { ws[t>>5] = s; wq[t>>5] = q; }
    __syncthreads();
    if (t == 0) {
        float S = 0.f, Q = 0.f;
        #pragma unroll
        for (int i = 0; i < 8; i++) { S += ws[i]; Q += wq[i]; }
        atomicAdd(&gsum[c], S);
        atomicAdd(&gsq[c], Q);
    }
}

// ---------------- BN3 + ReLU + max over K (h3 channel-major) -----------------
__global__ void maxpool_kernel(const float* __restrict__ gamma,
                               const float* __restrict__ beta,
                               float* __restrict__ out) {
    const int t = threadIdx.x;
    const int qi = t >> 2, og = t & 3;
    const int q = blockIdx.x * 32 + qi;
    const int b = q / SQ, s = q - b*SQ;
    const float invM = 1.0f / (float)MROWS;
    #pragma unroll 4
    for (int i = 0; i < 32; i++) {
        int o = og*32 + i;
        float mean = g_sum[256 + o] * invM;
        float var  = g_sq[256 + o] * invM - mean*mean;
        float rs = rsqrtf(var + BN_EPS);
        float sc = gamma[o] * rs;
        float sh = beta[o] - mean*sc;
        const float4* h = (const float4*)(g_h3 + (size_t)o * MROWS + (size_t)q * KNN);
        float mx = -3.402823466e38f;
        #pragma unroll
        for (int k = 0; k < 8; k++) {
            float4 x = h[k];
            mx = fmaxf(mx, fmaf(x.x, sc, sh));
            mx = fmaxf(mx, fmaf(x.y, sc, sh));
            mx = fmaxf(mx, fmaf(x.z, sc, sh));
            mx = fmaxf(mx, fmaf(x.w, sc, sh));
        }
        out[(size_t)(b*128 + o) * SQ + s] = fmaxf(mx, 0.f);
    }
}

// ---------------- launch ------------------------------------------------
extern "C" void kernel_launch(void* const* d_in, const int* in_sizes, int n_in,
                              void* d_out, int out_size) {
    const float* xyz    = (const float*)d_in[0];
    const float* points = (const float*)d_in[1];
    const float* newxyz = (const float*)d_in[2];
    const float* W1 = (const float*)d_in[3],  *b1 = (const float*)d_in[4];
    const float* ga1 = (const float*)d_in[5], *be1 = (const float*)d_in[6];
    const float* W2 = (const float*)d_in[7],  *b2 = (const float*)d_in[8];
    const float* ga2 = (const float*)d_in[9], *be2 = (const float*)d_in[10];
    const float* W3 = (const float*)d_in[11], *b3 = (const float*)d_in[12];
    const float* ga3 = (const float*)d_in[13], *be3 = (const float*)d_in[14];

    float* out = (float*)d_out;
    float* outPts = out;
    if (out_size == BQ*SQ*3 + BQ*128*SQ) {
        cudaMemcpyAsync(out, newxyz, sizeof(float)*BQ*SQ*3, cudaMemcpyDeviceToDevice);
        outPts = out + BQ*SQ*3;
    }

    float *h1, *h2, *h3, *gsum, *gsq;
    cudaGetSymbolAddress((void**)&h1, g_h1);
    cudaGetSymbolAddress((void**)&h2, g_h2);
    cudaGetSymbolAddress((void**)&h3, g_h3);
    cudaGetSymbolAddress((void**)&gsum, g_sum);
    cudaGetSymbolAddress((void**)&gsq, g_sq);

    const int SM1 = 128*KS1*2 + 64*KS1*2;      // 95,232 B
    const int SM2 = 128*KS23*2 + 64*KS23*2;    // 76,800 B
    const int SM3 = 128*KS23*2 + 128*KS23*2;   // 102,400 B
    cudaFuncSetAttribute(gemm1_tc,        cudaFuncAttributeMaxDynamicSharedMemorySize, SM1);
    cudaFuncSetAttribute(gemm_bn_tc<64>,  cudaFuncAttributeMaxDynamicSharedMemorySize, SM2);
    cudaFuncSetAttribute(gemm_bn_tc<128>, cudaFuncAttributeMaxDynamicSharedMemorySize, SM3);

    // Launch order: ncu (-s 5 -c 1) profiles #6 = layer-2 GEMM.
    zero_stats_kernel<<<1, 512>>>();                                    // 1
    ballquery_kernel<<<512, 256>>>(xyz, newxyz, 0);                     // 2
    ballquery_kernel<<<512, 256>>>(xyz, newxyz, 512);                   // 3
    gemm1_tc<<<MROWS/128, 256, SM1>>>(xyz, points, newxyz, W1, b1, h1); // 4
    stats_kernel<<<dim3(64,16), 256>>>(h1, gsum + 0, gsq + 0);          // 5
    gemm_bn_tc<64><<<MROWS/128, 256, SM2>>>(h1, W2, b2, ga1, be1,
                                            gsum + 0, gsq + 0, h2);     // 6
    stats_kernel<<<dim3(64,16), 256>>>(h2, gsum + 128, gsq + 128);      // 7
    gemm_bn_tc<128><<<MROWS/128, 256, SM3>>>(h2, W3, b3, ga2, be2,
                                             gsum + 128, gsq + 128, h3);// 8
    stats_kernel<<<dim3(128,16), 256>>>(h3, gsum + 256, gsq + 256);     // 9
    maxpool_kernel<<<NQTOT/32, 128>>>(ga3, be3, outPts);                // 10
}